// round 5
// baseline (speedup 1.0000x reference)
#include <cuda_runtime.h>
#include <cstdint>

// ============================================================================
// FrequencyToSpatialCrossAttention — fully fused attention pass.
//  k1 : Qg = mean(X_f)                                   read 402MB
//  k2 : A[b,c,h] (scale folded), zero g_y                tiny
//  k35: per-window fused scores+softmax+y, X_s read ONCE read 402MB
//       (cp.async double-buffered across windows; y in regs; atomics at end)
//  k6 : (Wv@y+bv)@Wo^T+bo                                tiny
//  k7 : broadcast                                        write 402MB
// ============================================================================

#define BATCH 4
#define CDIM  384
#define NH    8
#define NPIX  65536
#define XP    (384*68)          // one window buffer: 384 rows x 68-float pitch

typedef unsigned long long ull;

__device__ __forceinline__ ull pk(float x, float y) {
    ull r; asm("mov.b64 %0, {%1,%2};" : "=l"(r) : "f"(x), "f"(y)); return r;
}
__device__ __forceinline__ void upk(ull v, float& x, float& y) {
    asm("mov.b64 {%0,%1}, %2;" : "=f"(x), "=f"(y) : "l"(v));
}
__device__ __forceinline__ ull ffma2(ull a, ull b, ull c) {
    ull d; asm("fma.rn.f32x2 %0, %1, %2, %3;" : "=l"(d) : "l"(a), "l"(b), "l"(c));
    return d;
}
__device__ __forceinline__ uint32_t s2u(const void* p) {
    uint32_t a;
    asm("{ .reg .u64 t; cvta.to.shared.u64 t, %1; cvt.u32.u64 %0, t; }"
        : "=r"(a) : "l"(p));
    return a;
}
__device__ __forceinline__ void cpa16(uint32_t dst, const void* src) {
    asm volatile("cp.async.cg.shared.global [%0], [%1], 16;" :: "r"(dst), "l"(src));
}

__device__ float g_Qg [BATCH*CDIM];
__device__ float g_A  [BATCH*CDIM*NH];   // [b][c][h], scale folded
__device__ float g_y  [BATCH*NH*CDIM];
__device__ float g_out[BATCH*CDIM];

// ---------------------------------------------------------------- k1: Qg mean
__global__ void k1_mean(const float* __restrict__ Xf) {
    int bc = blockIdx.x;
    const float4* src = (const float4*)Xf + (size_t)bc * 16384;
    float s0 = 0.f, s1 = 0.f;
    #pragma unroll 8
    for (int i = threadIdx.x; i < 16384; i += 1024) {
        float4 a = src[i], b = src[i + 512];
        s0 += (a.x + a.y) + (a.z + a.w);
        s1 += (b.x + b.y) + (b.z + b.w);
    }
    float s = s0 + s1;
    __shared__ float red[512];
    red[threadIdx.x] = s;
    __syncthreads();
    for (int o = 256; o > 0; o >>= 1) {
        if (threadIdx.x < o) red[threadIdx.x] += red[threadIdx.x + o];
        __syncthreads();
    }
    if (threadIdx.x == 0) g_Qg[bc] = red[0] * (1.f / 65536.f);
}

// ------------------------------------------------- k2: Q proj + A, zero g_y
__global__ void k2_proj(const float* __restrict__ Wq, const float* __restrict__ bq,
                        const float* __restrict__ Wk) {
    int b = blockIdx.x, c = threadIdx.x;
    __shared__ float qf[CDIM];
    const float* qg = &g_Qg[b * CDIM];
    float acc = bq[c];
    for (int j = 0; j < CDIM; j++) acc += qg[j] * Wq[c * CDIM + j];
    qf[c] = acc;
    __syncthreads();
    const float scale = 0.14433756729740643f;   // 48^-0.5
    #pragma unroll
    for (int h = 0; h < NH; h++) {
        float a = 0.f;
        for (int d = 0; d < 48; d++) a += qf[h * 48 + d] * Wk[(h * 48 + d) * CDIM + c];
        g_A[(b * CDIM + c) * NH + h] = a * scale;
    }
    for (int i = threadIdx.x; i < NH * CDIM; i += CDIM) g_y[b * NH * CDIM + i] = 0.f;
}

// --------------------------------------------- k35: fused attention pass
// grid = 1024 blocks x 4 windows each (windows never cross batch: 1024 % 4 == 0).
// smem: x double-buffer 2*XP + A 3072 + score partials 4*8*68  (~225 KB).
__global__ void __launch_bounds__(512, 1) k35_fused(const float* __restrict__ Xs) {
    extern __shared__ float sm[];
    float* xs = sm;                   // [2][XP]
    float* sA = sm + 2 * XP;          // [384][8]
    float* sp = sA + CDIM * 8;        // [4*8][68]  partials; row [h][*] becomes weights

    int tid = threadIdx.x;
    int g0  = blockIdx.x * 4;         // first window id (global, 0..4095)
    int b   = g0 >> 10;
    const float* xbase = Xs + ((size_t)b * CDIM << 16);

    for (int i = tid; i < CDIM * 8; i += 512) sA[i] = g_A[b * CDIM * 8 + i];

    uint32_t xs_u = s2u(xs);

    // stage one window (6144 x 16B chunks) with nthr threads starting at t0
    auto stage = [&](int w, int buf, int t0, int nthr) {
        int wloc = w & 1023;
        int wy = wloc >> 5, wx = wloc & 31;
        int biy = wy * 8 + 252, bix = wx * 8 + 252;     // roll shift -4
        for (int m = tid - t0; m < 6144; m += nthr) {
            int c = m >> 4, seg = m & 15;
            int rr = seg >> 1, hf = seg & 1;
            int iy = (biy + rr) & 255;
            int ix = (bix + hf * 4) & 255;
            cpa16(xs_u + (uint32_t)(buf * XP + c * 68 + rr * 8 + hf * 4) * 4,
                  xbase + ((size_t)c << 16) + iy * 256 + ix);
        }
    };

    stage(g0, 0, 0, 512);
    asm volatile("cp.async.commit_group;");

    ull yacc[3][8];
    #pragma unroll
    for (int i = 0; i < 3; i++)
        #pragma unroll
        for (int h = 0; h < 8; h++) yacc[i][h] = pk(0.f, 0.f);

    int cg = tid >> 2, tg = tid & 3;

    for (int wi = 0; wi < 4; wi++) {
        int cur = wi & 1;
        asm volatile("cp.async.wait_group 0;" ::: "memory");
        __syncthreads();

        const float* xr = xs + cur * XP;

        if (tid >= 256) {
            if (wi < 3) {
                stage(g0 + wi + 1, cur ^ 1, 256, 256);
                asm volatile("cp.async.commit_group;");
            }
        } else {
            // scores: p = tid&63, c-quarter q = tid>>6 (96 channels each)
            int p = tid & 63, q = tid >> 6;
            ull a0 = pk(0.f,0.f), a1 = a0, a2 = a0, a3 = a0;
            int c0 = q * 96;
            const float* xq = xr + c0 * 68 + p;
            const ulonglong2* aq = (const ulonglong2*)&sA[c0 * 8];
            #pragma unroll 8
            for (int cc = 0; cc < 96; cc++) {
                float x = xq[cc * 68];
                ull x2 = pk(x, x);
                ulonglong2 A01 = aq[cc * 2];
                ulonglong2 A23 = aq[cc * 2 + 1];
                a0 = ffma2(x2, A01.x, a0);
                a1 = ffma2(x2, A01.y, a1);
                a2 = ffma2(x2, A23.x, a2);
                a3 = ffma2(x2, A23.y, a3);
            }
            float lo, hi;
            upk(a0, lo, hi); sp[(q*8+0)*68+p] = lo; sp[(q*8+1)*68+p] = hi;
            upk(a1, lo, hi); sp[(q*8+2)*68+p] = lo; sp[(q*8+3)*68+p] = hi;
            upk(a2, lo, hi); sp[(q*8+4)*68+p] = lo; sp[(q*8+5)*68+p] = hi;
            upk(a3, lo, hi); sp[(q*8+6)*68+p] = lo; sp[(q*8+7)*68+p] = hi;
        }
        __syncthreads();

        // softmax: warp h (warps 0-7); weights overwrite sp[h][*]
        if (tid < 256) {
            int h = tid >> 5, lane = tid & 31;
            float s0 = 0.f, s1 = 0.f;
            #pragma unroll
            for (int q = 0; q < 4; q++) {
                s0 += sp[(q*8+h)*68 + lane];
                s1 += sp[(q*8+h)*68 + lane + 32];
            }
            float m = fmaxf(s0, s1);
            #pragma unroll
            for (int o = 16; o > 0; o >>= 1)
                m = fmaxf(m, __shfl_xor_sync(0xffffffffu, m, o));
            float e0 = __expf(s0 - m), e1 = __expf(s1 - m);
            float Z = e0 + e1;
            #pragma unroll
            for (int o = 16; o > 0; o >>= 1)
                Z += __shfl_xor_sync(0xffffffffu, Z, o);
            float inv = 1.f / (Z * 1024.f);      // fold 1/nW
            sp[h*68 + lane]      = e0 * inv;
            sp[h*68 + lane + 32] = e1 * inv;
        }
        __syncthreads();

        // y: thread = (cg: 3 channels c=cg+128i, tg: 16 pixels), FFMA2-packed
        #pragma unroll
        for (int j = 0; j < 4; j++) {
            int pb = tg * 16 + j * 4;
            ull wl[8], wh[8];
            #pragma unroll
            for (int h = 0; h < 8; h++) {
                float4 wv = *(const float4*)&sp[h*68 + pb];
                wl[h] = pk(wv.x, wv.y); wh[h] = pk(wv.z, wv.w);
            }
            #pragma unroll
            for (int i = 0; i < 3; i++) {
                float4 xv = *(const float4*)&xr[(cg + 128*i)*68 + pb];
                ull xl = pk(xv.x, xv.y), xh = pk(xv.z, xv.w);
                #pragma unroll
                for (int h = 0; h < 8; h++)
                    yacc[i][h] = ffma2(xl, wl[h], ffma2(xh, wh[h], yacc[i][h]));
            }
        }
        // next iteration's wait+sync protects buffer reuse
    }

    // reduce tg (lane bits 0-1) and emit
    #pragma unroll
    for (int i = 0; i < 3; i++)
        #pragma unroll
        for (int h = 0; h < 8; h++) {
            float lo, hi; upk(yacc[i][h], lo, hi);
            float v = lo + hi;
            v += __shfl_xor_sync(0xffffffffu, v, 1);
            v += __shfl_xor_sync(0xffffffffu, v, 2);
            if (tg == 0)
                atomicAdd(&g_y[b * NH * CDIM + h * CDIM + cg + 128*i], v);
        }
}

// ----------------------------------------------------------- k6: tiny finals
__global__ void k6_out(const float* __restrict__ Wv, const float* __restrict__ bv,
                       const float* __restrict__ Wo, const float* __restrict__ bo) {
    int b = blockIdx.x, c = threadIdx.x;
    __shared__ float sy[NH * CDIM];
    __shared__ float pre[CDIM];
    for (int i = c; i < NH * CDIM; i += CDIM) sy[i] = g_y[b * NH * CDIM + i];
    __syncthreads();
    int h = c / 48;
    float a = bv[c];
    for (int j = 0; j < CDIM; j++) a += Wv[c * CDIM + j] * sy[h * CDIM + j];
    pre[c] = a;
    __syncthreads();
    float o = bo[c];
    for (int j = 0; j < CDIM; j++) o += Wo[c * CDIM + j] * pre[j];
    g_out[b * CDIM + c] = o;
}

// ------------------------------------------------------------- k7: broadcast
__global__ void k7_bcast(float* __restrict__ out) {
    int plane = blockIdx.x;
    int q = blockIdx.y;
    float v = g_out[plane];
    float4 vv = make_float4(v, v, v, v);
    float4* dst = (float4*)out + (size_t)plane * 16384 + q * 4096;
    #pragma unroll 4
    for (int i = threadIdx.x; i < 4096; i += 256) dst[i] = vv;
}

// ============================================================================
extern "C" void kernel_launch(void* const* d_in, const int* in_sizes, int n_in,
                              void* d_out, int out_size) {
    const float* Xf = (const float*)d_in[0];
    const float* Xs = (const float*)d_in[1];
    const float* Wq = (const float*)d_in[2];
    const float* bq = (const float*)d_in[3];
    const float* Wk = (const float*)d_in[4];
    // d_in[5] = bk: constant per (b,h) in scores, cancels in softmax
    const float* Wv = (const float*)d_in[6];
    const float* bv = (const float*)d_in[7];
    const float* Wo = (const float*)d_in[8];
    const float* bo = (const float*)d_in[9];

    const int smem35 = (2 * XP + CDIM * 8 + 4 * 8 * 68) * 4;   // 229,888 B
    cudaFuncSetAttribute(k35_fused, cudaFuncAttributeMaxDynamicSharedMemorySize,
                         smem35);

    k1_mean  <<<BATCH * CDIM, 512>>>(Xf);
    k2_proj  <<<BATCH, CDIM>>>(Wq, bq, Wk);
    k35_fused<<<1024, 512, smem35>>>(Xs);
    k6_out   <<<BATCH, CDIM>>>(Wv, bv, Wo, bo);
    k7_bcast <<<dim3(BATCH * CDIM, 4), 256>>>((float*)d_out);
}

// round 6
// speedup vs baseline: 1.9585x; 1.9585x over previous
#include <cuda_runtime.h>
#include <cstdint>

// ============================================================================
// FrequencyToSpatialCrossAttention — split pipeline, latency bugs fixed.
//  k1 : Qg = mean(X_f)                          read 402MB
//  k2a: qf = Qg@Wq^T+bq   (warp-per-row, coalesced)   tiny
//  k2b: A[b,c,h] = scale*qf_h.Wk_h[:,c]; zero g_y     tiny
//  k3 : scores+softmax, 1px/thread              read 402MB
//  k5 : y accum, cp.async double-buffered       read 402MB
//  k6a: pre = Wv@y+bv     (warp-per-row, coalesced)   tiny
//  k6b: out = Wo@pre+bo                               tiny
//  k7 : broadcast                               write 402MB
// ============================================================================

#define BATCH 4
#define CDIM  384
#define NH    8
#define NPIX  65536
#define NWIN  1024

typedef unsigned long long ull;

__device__ __forceinline__ ull pk(float x, float y) {
    ull r; asm("mov.b64 %0, {%1,%2};" : "=l"(r) : "f"(x), "f"(y)); return r;
}
__device__ __forceinline__ void upk(ull v, float& x, float& y) {
    asm("mov.b64 {%0,%1}, %2;" : "=f"(x), "=f"(y) : "l"(v));
}
__device__ __forceinline__ ull ffma2(ull a, ull b, ull c) {
    ull d; asm("fma.rn.f32x2 %0, %1, %2, %3;" : "=l"(d) : "l"(a), "l"(b), "l"(c));
    return d;
}
__device__ __forceinline__ uint32_t s2u(const void* p) {
    uint32_t a;
    asm("{ .reg .u64 t; cvta.to.shared.u64 t, %1; cvt.u32.u64 %0, t; }"
        : "=r"(a) : "l"(p));
    return a;
}
__device__ __forceinline__ void cpa16(uint32_t dst, const void* src) {
    asm volatile("cp.async.cg.shared.global [%0], [%1], 16;" :: "r"(dst), "l"(src));
}

__device__ float g_S  [BATCH*NH*NPIX];   // softmaxed weights, windowed layout
__device__ float g_Qg [BATCH*CDIM];
__device__ float g_qf [BATCH*CDIM];
__device__ float g_A  [BATCH*CDIM*NH];   // [b][c][h], scale folded
__device__ float g_y  [BATCH*NH*CDIM];
__device__ float g_pre[BATCH*CDIM];
__device__ float g_out[BATCH*CDIM];

// ---------------------------------------------------------------- k1: Qg mean
__global__ void k1_mean(const float* __restrict__ Xf) {
    int bc = blockIdx.x;
    const float4* src = (const float4*)Xf + (size_t)bc * 16384;
    float s0 = 0.f, s1 = 0.f;
    #pragma unroll 8
    for (int i = threadIdx.x; i < 16384; i += 1024) {
        float4 a = src[i], b = src[i + 512];
        s0 += (a.x + a.y) + (a.z + a.w);
        s1 += (b.x + b.y) + (b.z + b.w);
    }
    float s = s0 + s1;
    __shared__ float red[512];
    red[threadIdx.x] = s;
    __syncthreads();
    for (int o = 256; o > 0; o >>= 1) {
        if (threadIdx.x < o) red[threadIdx.x] += red[threadIdx.x + o];
        __syncthreads();
    }
    if (threadIdx.x == 0) g_Qg[bc] = red[0] * (1.f / 65536.f);
}

// -------------------------------------- k2a: qf = Qg@Wq^T + bq  (coalesced)
// grid (4,12), block 256 = 8 warps x 4 rows each.
__global__ void k2a(const float* __restrict__ Wq, const float* __restrict__ bq) {
    int b = blockIdx.x, tid = threadIdx.x;
    __shared__ float sq[CDIM];
    for (int i = tid; i < CDIM; i += 256) sq[i] = g_Qg[b * CDIM + i];
    __syncthreads();
    int wid = tid >> 5, lane = tid & 31;
    #pragma unroll
    for (int cc = 0; cc < 4; cc++) {
        int c = blockIdx.y * 32 + wid * 4 + cc;
        const float* w = Wq + (size_t)c * CDIM;
        float s = 0.f;
        #pragma unroll
        for (int k = 0; k < 12; k++) s += w[lane + 32 * k] * sq[lane + 32 * k];
        #pragma unroll
        for (int o = 16; o > 0; o >>= 1) s += __shfl_xor_sync(0xffffffffu, s, o);
        if (lane == 0) g_qf[b * CDIM + c] = s + bq[c];
    }
}

// ----------------- k2b: A[b,c,h] = scale * qf_h . Wk_h[:,c]; zero g_y
// grid (4,12), block 256 = 32 c-lanes x 8 heads; Wk loads lane-contiguous.
__global__ void k2b(const float* __restrict__ Wk) {
    int b = blockIdx.x, tid = threadIdx.x;
    __shared__ float sq[CDIM];
    for (int i = tid; i < CDIM; i += 256) sq[i] = g_qf[b * CDIM + i];
    __syncthreads();
    int c = blockIdx.y * 32 + (tid & 31);
    int h = tid >> 5;
    float a = 0.f;
    #pragma unroll 8
    for (int d = 0; d < 48; d++)
        a += sq[h * 48 + d] * Wk[(size_t)(h * 48 + d) * CDIM + c];
    g_A[(size_t)(b * CDIM + c) * 8 + h] = a * 0.14433756729740643f;  // 48^-0.5
    if (blockIdx.y == 0)
        for (int i = tid; i < NH * CDIM; i += 256) g_y[b * NH * CDIM + i] = 0.f;
}

// ------------------------- k3: scores + softmax; strip = 8 rows x 32 cols
__global__ void __launch_bounds__(256, 4) k3_scores(const float* __restrict__ Xs) {
    int bx   = blockIdx.x;
    int b    = bx >> 8;
    int sidx = bx & 255;
    int sr   = sidx >> 3;
    int scol = sidx & 7;
    int t = threadIdx.x;
    int r = t >> 5, col = t & 31;

    __shared__ float sA[CDIM * 8];
    __shared__ float sS[8 * 264];

    for (int i = t; i < CDIM * 8; i += 256) sA[i] = g_A[b * CDIM * 8 + i];
    __syncthreads();

    int ii = sr * 8 + r;
    int jj = scol * 32 + col;
    int si = (ii + 252) & 255;
    int sj = (jj + 252) & 255;
    const float* xp = Xs + (size_t)b * CDIM * NPIX + si * 256 + sj;

    ull acc[4];
    #pragma unroll
    for (int q = 0; q < 4; q++) acc[q] = pk(0.f, 0.f);

    const ulonglong2* sA2 = (const ulonglong2*)sA;
    #pragma unroll 8
    for (int c = 0; c < CDIM; c++) {
        float x = xp[(size_t)c << 16];
        ull x2 = pk(x, x);
        ulonglong2 a01 = sA2[c * 2];
        ulonglong2 a23 = sA2[c * 2 + 1];
        acc[0] = ffma2(x2, a01.x, acc[0]);
        acc[1] = ffma2(x2, a01.y, acc[1]);
        acc[2] = ffma2(x2, a23.x, acc[2]);
        acc[3] = ffma2(x2, a23.y, acc[3]);
    }

    int p = r * 32 + col;
    #pragma unroll
    for (int q = 0; q < 4; q++) {
        float lo, hi; upk(acc[q], lo, hi);
        sS[(2 * q) * 264 + p]     = lo;
        sS[(2 * q + 1) * 264 + p] = hi;
    }
    __syncthreads();

    if (t < 64) {
        int pair = t >> 1, sub = t & 1;
        int h = pair >> 2, win = pair & 3;
        int base = h * 264 + win * 8;
        float4 v[8];
        #pragma unroll
        for (int rr = 0; rr < 4; rr++) {
            int off = base + (sub * 4 + rr) * 32;
            v[rr * 2]     = *(const float4*)&sS[off];
            v[rr * 2 + 1] = *(const float4*)&sS[off + 4];
        }
        float m = -1e30f;
        #pragma unroll
        for (int q = 0; q < 8; q++)
            m = fmaxf(m, fmaxf(fmaxf(v[q].x, v[q].y), fmaxf(v[q].z, v[q].w)));
        m = fmaxf(m, __shfl_xor_sync(0xffffffffu, m, 1));
        float Z = 0.f;
        #pragma unroll
        for (int q = 0; q < 8; q++) {
            v[q].x = __expf(v[q].x - m); v[q].y = __expf(v[q].y - m);
            v[q].z = __expf(v[q].z - m); v[q].w = __expf(v[q].w - m);
            Z += (v[q].x + v[q].y) + (v[q].z + v[q].w);
        }
        Z += __shfl_xor_sync(0xffffffffu, Z, 1);
        float inv = 1.f / (Z * 1024.f);

        int gwin = sr * 32 + scol * 4 + win;
        size_t gbase = ((size_t)(b * 8 + h) * NWIN + gwin) * 64;
        #pragma unroll
        for (int rr = 0; rr < 4; rr++) {
            int rloc = (sub * 4 + rr) * 8;
            float4 e0 = v[rr * 2], e1 = v[rr * 2 + 1];
            e0.x *= inv; e0.y *= inv; e0.z *= inv; e0.w *= inv;
            e1.x *= inv; e1.y *= inv; e1.z *= inv; e1.w *= inv;
            *(float4*)&g_S[gbase + rloc]     = e0;
            *(float4*)&g_S[gbase + rloc + 4] = e1;
        }
    }
}

// ---------------------------------------------------------------- k5: y accum
__global__ void __launch_bounds__(256) k5_y(const float* __restrict__ Xs) {
    int unit = blockIdx.x;
    int b = unit / 72;
    int rem = unit % 72;
    int cchunk = rem / 12;
    int s = rem % 12;
    int cc0 = cchunk * 64;
    int t0 = (s * 1024) / 12, t1 = ((s + 1) * 1024) / 12;

    __shared__ float xt[2][64 * 68];
    __shared__ float wt[2][8 * 68];

    int tid = threadIdx.x;
    int cg = tid & 15, tg = tid >> 4;
    int lane = tid & 31, wid = tid >> 5;

    const float4* xsp0 = (const float4*)Xs + (size_t)(b * CDIM + cc0) * 16384;
    uint32_t xt_u[2] = { s2u(&xt[0][0]), s2u(&xt[1][0]) };
    uint32_t wt_u[2] = { s2u(&wt[0][0]), s2u(&wt[1][0]) };

    ull acc[4][8];
    #pragma unroll
    for (int i = 0; i < 4; i++)
        #pragma unroll
        for (int h = 0; h < 8; h++) acc[i][h] = pk(0.f, 0.f);

    auto stage = [&](int tile, int buf) {
        #pragma unroll
        for (int j = 0; j < 4; j++) {
            int i = tid + j * 256;
            int c = i >> 4, tf4 = i & 15;
            cpa16(xt_u[buf] + (c * 68 + tf4 * 4) * 4,
                  xsp0 + (size_t)c * 16384 + tile * 16 + tf4);
        }
        if (tid < 128) {
            int h = tid >> 4, tf4 = tid & 15;
            int p = tile * 64 + tf4 * 4;
            int sy = p >> 8, sx = p & 255;
            int iy = (sy + 4) & 255, ix = (sx + 4) & 255;
            size_t idx = ((size_t)(b * 8 + h) * NWIN + (iy >> 3) * 32 + (ix >> 3)) * 64
                         + (iy & 7) * 8 + (ix & 7);
            cpa16(wt_u[buf] + (h * 68 + tf4 * 4) * 4, &g_S[idx]);
        }
    };

    int nt = t1 - t0;
    stage(t0, 0);
    asm volatile("cp.async.commit_group;");

    int t4 = tg * 4;
    for (int k = 0; k < nt; k++) {
        asm volatile("cp.async.wait_group 0;" ::: "memory");
        __syncthreads();
        if (k + 1 < nt) {
            stage(t0 + k + 1, (k + 1) & 1);
            asm volatile("cp.async.commit_group;");
        }
        int buf = k & 1;
        const float* xb = xt[buf];
        const float* wb = wt[buf];
        ull wlo[8], whi[8];
        #pragma unroll
        for (int h = 0; h < 8; h++) {
            float4 wv = *(const float4*)&wb[h * 68 + t4];
            wlo[h] = pk(wv.x, wv.y); whi[h] = pk(wv.z, wv.w);
        }
        #pragma unroll
        for (int i = 0; i < 4; i++) {
            float4 xv = *(const float4*)&xb[(cg + i * 16) * 68 + t4];
            ull xlo = pk(xv.x, xv.y), xhi = pk(xv.z, xv.w);
            #pragma unroll
            for (int h = 0; h < 8; h++) {
                acc[i][h] = ffma2(xlo, wlo[h], acc[i][h]);
                acc[i][h] = ffma2(xhi, whi[h], acc[i][h]);
            }
        }
    }
    __syncthreads();

    float* sred = &xt[0][0];
    #pragma unroll
    for (int i = 0; i < 4; i++)
        #pragma unroll
        for (int h = 0; h < 8; h++) {
            float lo, hi; upk(acc[i][h], lo, hi);
            float vsum = lo + hi;
            vsum += __shfl_xor_sync(0xffffffffu, vsum, 16);
            if (lane < 16) sred[wid * 512 + i * 128 + h * 16 + lane] = vsum;
        }
    __syncthreads();
    #pragma unroll
    for (int o = tid; o < 512; o += 256) {
        float sm = 0.f;
        #pragma unroll
        for (int w = 0; w < 8; w++) sm += sred[w * 512 + o];
        int i = o >> 7, h = (o >> 4) & 7, c = cc0 + (o & 15) + 16 * i;
        atomicAdd(&g_y[b * NH * CDIM + h * CDIM + c], sm);
    }
}

// ---------------------------- k6a: pre = Wv@y + bv   (warp-per-row, coalesced)
__global__ void k6a(const float* __restrict__ Wv, const float* __restrict__ bv) {
    int b = blockIdx.x, tid = threadIdx.x;
    __shared__ float sy[NH * CDIM];
    for (int i = tid; i < NH * CDIM; i += 256) sy[i] = g_y[b * NH * CDIM + i];
    __syncthreads();
    int wid = tid >> 5, lane = tid & 31;
    #pragma unroll
    for (int cc = 0; cc < 4; cc++) {
        int c = blockIdx.y * 32 + wid * 4 + cc;
        int h = c / 48;
        const float* w = Wv + (size_t)c * CDIM;
        const float* yy = &sy[h * CDIM];
        float s = 0.f;
        #pragma unroll
        for (int k = 0; k < 12; k++) s += w[lane + 32 * k] * yy[lane + 32 * k];
        #pragma unroll
        for (int o = 16; o > 0; o >>= 1) s += __shfl_xor_sync(0xffffffffu, s, o);
        if (lane == 0) g_pre[b * CDIM + c] = s + bv[c];
    }
}

// ---------------------------- k6b: out = Wo@pre + bo
__global__ void k6b(const float* __restrict__ Wo, const float* __restrict__ bo) {
    int b = blockIdx.x, tid = threadIdx.x;
    __shared__ float sp[CDIM];
    for (int i = tid; i < CDIM; i += 256) sp[i] = g_pre[b * CDIM + i];
    __syncthreads();
    int wid = tid >> 5, lane = tid & 31;
    #pragma unroll
    for (int cc = 0; cc < 4; cc++) {
        int c = blockIdx.y * 32 + wid * 4 + cc;
        const float* w = Wo + (size_t)c * CDIM;
        float s = 0.f;
        #pragma unroll
        for (int k = 0; k < 12; k++) s += w[lane + 32 * k] * sp[lane + 32 * k];
        #pragma unroll
        for (int o = 16; o > 0; o >>= 1) s += __shfl_xor_sync(0xffffffffu, s, o);
        if (lane == 0) g_out[b * CDIM + c] = s + bo[c];
    }
}

// ------------------------------------------------------------- k7: broadcast
__global__ void k7_bcast(float* __restrict__ out) {
    int plane = blockIdx.x;
    int q = blockIdx.y;
    float v = g_out[plane];
    float4 vv = make_float4(v, v, v, v);
    float4* dst = (float4*)out + (size_t)plane * 16384 + q * 4096;
    #pragma unroll 4
    for (int i = threadIdx.x; i < 4096; i += 256) dst[i] = vv;
}

// ============================================================================
extern "C" void kernel_launch(void* const* d_in, const int* in_sizes, int n_in,
                              void* d_out, int out_size) {
    const float* Xf = (const float*)d_in[0];
    const float* Xs = (const float*)d_in[1];
    const float* Wq = (const float*)d_in[2];
    const float* bq = (const float*)d_in[3];
    const float* Wk = (const float*)d_in[4];
    // d_in[5] = bk: constant per (b,h) in scores, cancels in softmax
    const float* Wv = (const float*)d_in[6];
    const float* bv = (const float*)d_in[7];
    const float* Wo = (const float*)d_in[8];
    const float* bo = (const float*)d_in[9];

    k1_mean  <<<BATCH * CDIM, 512>>>(Xf);
    k2a      <<<dim3(BATCH, 12), 256>>>(Wq, bq);
    k2b      <<<dim3(BATCH, 12), 256>>>(Wk);
    k3_scores<<<BATCH * 256, 256>>>(Xs);
    k5_y     <<<288, 256>>>(Xs);
    k6a      <<<dim3(BATCH, 12), 256>>>(Wv, bv);
    k6b      <<<dim3(BATCH, 12), 256>>>(Wo, bo);
    k7_bcast <<<dim3(BATCH * CDIM, 4), 256>>>((float*)d_out);
}